// round 12
// baseline (speedup 1.0000x reference)
#include <cuda_runtime.h>
#include <cuda_fp16.h>
#include <cstdint>
#include <cstddef>

// ---------------------------------------------------------------------------
// Fused concat-linear, single-pass FP16 mma.sync.m16n8k16 (fp32 accumulate).
// R12: A fragments loaded straight from packed gmem via LDG.128 (L1/L2
// resident); smem pipeline carries B only (16KB stages, 4 deep). Crossbar
// traffic and LSU issue per kt halved vs R11; barrier structure unchanged.
//   y[m,o] = sum_k x[m,k] W[o,k] + b[o];  M=8192 N=12288 K=4096
//   out = 3 segments of H=4096 along o.
// ---------------------------------------------------------------------------

#define MDIM 8192
#define NDIM 12288
#define KDIM 4096
#define HDIM 4096

static constexpr int STAGES = 4;
static constexpr int THREADS = 128;

static constexpr int MT16 = MDIM / 16;        // 512
static constexpr int NT16 = NDIM / 16;        // 768
static constexpr int KC16 = KDIM / 16;        // 256

// packed half2-word scratch, fragment-ordered (validated R10/R11):
// A unit (kc16, mt16): 32 lanes x 4 words {a0,a1,a2,a3} of m16n8k16.row
// B unit (kc16, nt16): 32 lanes x 4 words {b0lo,b1lo,b0hi,b1hi}
__device__ uint32_t g_Apack[(size_t)KC16 * MT16 * 128];   // 67 MB
__device__ uint32_t g_Bpack[(size_t)KC16 * NT16 * 128];   // 100 MB

static constexpr int STAGE_WORDS = 4096;                       // B only, 16KB
static constexpr int SMEM_BYTES  = STAGES * STAGE_WORDS * 4;   // 65536

static constexpr int TILES_M = MDIM / 128;    // 64
static constexpr int TILES_N = NDIM / 128;    // 96
static constexpr int GROUP_M = 32;

static constexpr int A_PACK_BLOCKS = 16384;   // 4194304 threads
static constexpr int B_PACK_BLOCKS = 24576;   // 6291456 threads

__device__ __forceinline__ uint32_t smem_u32(const void* p) {
    return (uint32_t)__cvta_generic_to_shared(p);
}
__device__ __forceinline__ void cp16(uint32_t dst, const void* src) {
    asm volatile("cp.async.cg.shared.global [%0], [%1], 16;" :: "r"(dst), "l"(src));
}
__device__ __forceinline__ uint32_t h2pack(float lo, float hi) {
    __half2 h = __floats2half2_rn(lo, hi);
    return *reinterpret_cast<uint32_t*>(&h);
}
__device__ __forceinline__ void mma_f16(float* c, const uint32_t* a,
                                        uint32_t b0, uint32_t b1) {
    asm volatile(
        "mma.sync.aligned.m16n8k16.row.col.f32.f16.f16.f32 "
        "{%0,%1,%2,%3}, {%4,%5,%6,%7}, {%8,%9}, {%0,%1,%2,%3};"
        : "+f"(c[0]), "+f"(c[1]), "+f"(c[2]), "+f"(c[3])
        : "r"(a[0]), "r"(a[1]), "r"(a[2]), "r"(a[3]), "r"(b0), "r"(b1));
}

// ---------------- fused pack kernel (unchanged, validated R11) ----------------
__global__ __launch_bounds__(256)
void pack_ab(const float* __restrict__ xsrc, const float* __restrict__ wsrc,
             uint32_t* __restrict__ dstA, uint32_t* __restrict__ dstB) {
    if (blockIdx.x < A_PACK_BLOCKS) {
        const uint32_t idx = blockIdx.x * 256u + threadIdx.x;    // < 4194304
        const int lane = idx & 31;
        const uint32_t unit = idx >> 5;
        const int mt   = unit & 511;
        const int kc16 = unit >> 9;
        const int gid = lane >> 2, tig = lane & 3;

        const float* r0 = xsrc + (size_t)(mt * 16 + gid) * KDIM + kc16 * 16 + 2 * tig;
        const float* r1 = r0 + 8 * (size_t)KDIM;
        float2 v00 = *reinterpret_cast<const float2*>(r0);
        float2 v01 = *reinterpret_cast<const float2*>(r0 + 8);
        float2 v10 = *reinterpret_cast<const float2*>(r1);
        float2 v11 = *reinterpret_cast<const float2*>(r1 + 8);

        uint4 w;
        w.x = h2pack(v00.x, v00.y);   // a0
        w.y = h2pack(v10.x, v10.y);   // a1
        w.z = h2pack(v01.x, v01.y);   // a2
        w.w = h2pack(v11.x, v11.y);   // a3
        reinterpret_cast<uint4*>(dstA)[idx] = w;
    } else {
        const uint32_t idx = (blockIdx.x - A_PACK_BLOCKS) * 256u + threadIdx.x;
        const int lane = idx & 31;
        const uint32_t unit = idx >> 5;
        const int nt   = unit % 768;
        const int kc16 = unit / 768;
        const int gid = lane >> 2, tig = lane & 3;

        const float* r0 = wsrc + (size_t)(nt * 16 + gid) * KDIM + kc16 * 16 + 2 * tig;
        const float* r1 = r0 + 8 * (size_t)KDIM;
        float2 v00 = *reinterpret_cast<const float2*>(r0);
        float2 v01 = *reinterpret_cast<const float2*>(r0 + 8);
        float2 v10 = *reinterpret_cast<const float2*>(r1);
        float2 v11 = *reinterpret_cast<const float2*>(r1 + 8);

        uint4 w;
        w.x = h2pack(v00.x, v00.y);   // b0 lower n8
        w.y = h2pack(v01.x, v01.y);   // b1 lower n8
        w.z = h2pack(v10.x, v10.y);   // b0 upper n8
        w.w = h2pack(v11.x, v11.y);   // b1 upper n8
        reinterpret_cast<uint4*>(dstB)[idx] = w;
    }
}

// ---------------- GEMM: 128x128 tile, BK=64, 4 warps of 64x64 ----------------
// smem: B only, stage = [kc16(4)][ntile(8)][lane(32)][q(4)] words = 16KB.
// A fragments: direct LDG.128 from g_Apack (L1/L2-resident within a band).
__global__ __launch_bounds__(THREADS, 2)
void gemm_f16(const uint32_t* __restrict__ Apack,
              const uint32_t* __restrict__ Bpack,
              const float* __restrict__ bias,
              float* __restrict__ out)
{
    extern __shared__ uint32_t smemu[];
    const uint32_t sbase = smem_u32(smemu);

    const int tid  = threadIdx.x;
    const int wid  = tid >> 5;
    const int lane = tid & 31;
    const int gid  = lane >> 2;
    const int tig  = lane & 3;
    const int warp_m = wid & 1;     // 64 rows
    const int warp_n = wid >> 1;    // 64 cols

    const int bid  = blockIdx.x;
    const int band = bid / (GROUP_M * TILES_N);
    const int rem  = bid % (GROUP_M * TILES_N);
    const int mt   = band * GROUP_M + (rem % GROUP_M);
    const int nt   = rem / GROUP_M;
    const int m0 = mt * 128;
    const int n0 = nt * 128;

    const int ntBase  = n0 >> 4;                 // 8 consecutive B units per kc16
    const int mtBaseA = (m0 >> 4) + warp_m * 4;  // this warp's 4 A units per kc16

    // A fragment pointer: (kt, ks, mi) -> lane's 16B
    auto a_ptr = [&](int kt, int ks, int mi) {
        return reinterpret_cast<const uint4*>(
                   Apack + ((size_t)(4 * kt + ks) * MT16 + mtBaseA + mi) * 128) + lane;
    };

    float acc[4][8][4];
#pragma unroll
    for (int mi = 0; mi < 4; mi++)
#pragma unroll
        for (int ni = 0; ni < 8; ni++)
#pragma unroll
            for (int q = 0; q < 4; q++) acc[mi][ni][q] = 0.0f;

    const int KT = KDIM / 64;       // 64
    const int bBase = warp_n * 4;

    // B-only stage loader: 8 cp16 per thread
    auto load_stage = [&](int slot, int kt) {
        const uint32_t sB = sbase + (uint32_t)(slot * STAGE_WORDS) * 4;
#pragma unroll
        for (int kc = 0; kc < 4; kc++) {
            const uint32_t* bS = Bpack + ((size_t)(4 * kt + kc) * NT16 + ntBase) * 128;
            cp16(sB + kc * 4096 + tid * 32,      bS + tid * 8);
            cp16(sB + kc * 4096 + tid * 32 + 16, bS + tid * 8 + 4);
        }
        asm volatile("cp.async.commit_group;" ::: "memory");
    };

#pragma unroll
    for (int s = 0; s < STAGES - 1; s++) load_stage(s, s);

    uint4 af[2][4], bf[2][4];

    // A(0, ks0) has no barrier dependency — issue immediately
#pragma unroll
    for (int mi = 0; mi < 4; mi++) af[0][mi] = a_ptr(0, 0, mi)[0];

    asm volatile("cp.async.wait_group %0;" :: "n"(STAGES - 2) : "memory");
    __syncthreads();
    {
        const uint32_t* bs = smemu;
#pragma unroll
        for (int nj = 0; nj < 4; nj++)
            bf[0][nj] = *reinterpret_cast<const uint4*>(
                bs + (bBase + nj) * 128 + lane * 4);
    }

    for (int kt = 0; kt < KT; kt++) {
        const uint32_t* bs = smemu + (kt % STAGES) * STAGE_WORDS;

        const int kin = kt + STAGES - 1;
        if (kin < KT) load_stage(kin % STAGES, kin);
        else asm volatile("cp.async.commit_group;" ::: "memory");

        // ---- ks = 0..2: prefetch next frags (A: gmem, B: smem), compute current ----
#pragma unroll
        for (int ks = 0; ks < 3; ks++) {
            const int cur = ks & 1;
            const int nxt = cur ^ 1;
#pragma unroll
            for (int mi = 0; mi < 4; mi++)
                af[nxt][mi] = a_ptr(kt, ks + 1, mi)[0];
#pragma unroll
            for (int nj = 0; nj < 4; nj++)
                bf[nxt][nj] = *reinterpret_cast<const uint4*>(
                    bs + ((ks + 1) * 8 + bBase + nj) * 128 + lane * 4);
#pragma unroll
            for (int mi = 0; mi < 4; mi++) {
                const uint32_t afr[4] = {af[cur][mi].x, af[cur][mi].y,
                                         af[cur][mi].z, af[cur][mi].w};
#pragma unroll
                for (int nj = 0; nj < 4; nj++) {
                    mma_f16(acc[mi][nj * 2 + 0], afr, bf[cur][nj].x, bf[cur][nj].y);
                    mma_f16(acc[mi][nj * 2 + 1], afr, bf[cur][nj].z, bf[cur][nj].w);
                }
            }
        }

        // ---- stage-kt smem reads done; publish stage kt+1, license slot reuse ----
        asm volatile("cp.async.wait_group %0;" :: "n"(STAGES - 2) : "memory");
        __syncthreads();

        // ---- prefetch (kt+1, ks0): A from gmem, B from published stage kt+1 ----
        if (kt + 1 < KT) {
#pragma unroll
            for (int mi = 0; mi < 4; mi++)
                af[0][mi] = a_ptr(kt + 1, 0, mi)[0];
            const uint32_t* bs2 = smemu + ((kt + 1) % STAGES) * STAGE_WORDS;
#pragma unroll
            for (int nj = 0; nj < 4; nj++)
                bf[0][nj] = *reinterpret_cast<const uint4*>(
                    bs2 + (bBase + nj) * 128 + lane * 4);
        }

        // ---- ks = 3 MMAs (buf1), covering the prefetch latency ----
#pragma unroll
        for (int mi = 0; mi < 4; mi++) {
            const uint32_t afr[4] = {af[1][mi].x, af[1][mi].y,
                                     af[1][mi].z, af[1][mi].w};
#pragma unroll
            for (int nj = 0; nj < 4; nj++) {
                mma_f16(acc[mi][nj * 2 + 0], afr, bf[1][nj].x, bf[1][nj].y);
                mma_f16(acc[mi][nj * 2 + 1], afr, bf[1][nj].z, bf[1][nj].w);
            }
        }
    }

    // ---- epilogue: bias + segmented store (unchanged) ----
    const int seg  = n0 / HDIM;
    const int nloc = n0 % HDIM;
    float* outseg = out + (size_t)seg * MDIM * HDIM;

#pragma unroll
    for (int ni = 0; ni < 8; ni++) {
        const int cofs = warp_n * 64 + (ni >> 1) * 16 + (ni & 1) * 8 + 2 * tig;
        const float b0 = __ldg(bias + n0 + cofs);
        const float b1 = __ldg(bias + n0 + cofs + 1);
        const int cn = nloc + cofs;
#pragma unroll
        for (int mi = 0; mi < 4; mi++) {
            const int gm = m0 + warp_m * 64 + mi * 16 + gid;
            float2 v0, v1;
            v0.x = acc[mi][ni][0] + b0;  v0.y = acc[mi][ni][1] + b1;
            v1.x = acc[mi][ni][2] + b0;  v1.y = acc[mi][ni][3] + b1;
            *reinterpret_cast<float2*>(outseg + (size_t)gm * HDIM + cn)       = v0;
            *reinterpret_cast<float2*>(outseg + (size_t)(gm + 8) * HDIM + cn) = v1;
        }
    }
}

extern "C" void kernel_launch(void* const* d_in, const int* in_sizes, int n_in,
                              void* d_out, int out_size)
{
    const float* x = (const float*)d_in[0];
    const float* W = (const float*)d_in[1];
    const float* b = (const float*)d_in[2];
    float* out = (float*)d_out;

    void *ap, *bp;
    cudaGetSymbolAddress(&ap, g_Apack);
    cudaGetSymbolAddress(&bp, g_Bpack);

    pack_ab<<<A_PACK_BLOCKS + B_PACK_BLOCKS, 256>>>(
        x, W, (uint32_t*)ap, (uint32_t*)bp);

    cudaFuncSetAttribute(gemm_f16, cudaFuncAttributeMaxDynamicSharedMemorySize, SMEM_BYTES);
    gemm_f16<<<TILES_M * TILES_N, THREADS, SMEM_BYTES>>>(
        (const uint32_t*)ap, (const uint32_t*)bp, b, out);
}

// round 13
// speedup vs baseline: 1.0841x; 1.0841x over previous
#include <cuda_runtime.h>
#include <cuda_fp16.h>
#include <cstdint>
#include <cstddef>

// ---------------------------------------------------------------------------
// Fused concat-linear, single-pass FP16 mma.sync.m16n8k16 (fp32 accumulate),
// fragment-packed operands. R13 = R11 GEMM core verbatim (87.4% tensor,
// proven 1630us) + kc16-paired pack kernel (full-sector DRAM reads, 2x MLP).
//   y[m,o] = sum_k x[m,k] W[o,k] + b[o];  M=8192 N=12288 K=4096
//   out = 3 segments of H=4096 along o.
// ---------------------------------------------------------------------------

#define MDIM 8192
#define NDIM 12288
#define KDIM 4096
#define HDIM 4096

static constexpr int STAGES = 3;
static constexpr int THREADS = 128;

static constexpr int MT16 = MDIM / 16;        // 512
static constexpr int NT16 = NDIM / 16;        // 768
static constexpr int KC16 = KDIM / 16;        // 256

// packed half2-word scratch, fragment-ordered (validated R10/R11):
// A unit (kc16, mt16): 32 lanes x 4 words {a0,a1,a2,a3} of m16n8k16.row
// B unit (kc16, nt16): 32 lanes x 4 words {b0lo,b1lo,b0hi,b1hi}
__device__ uint32_t g_Apack[(size_t)KC16 * MT16 * 128];   // 67 MB
__device__ uint32_t g_Bpack[(size_t)KC16 * NT16 * 128];   // 100 MB

static constexpr int STAGE_WORDS = 8192;                       // A 16KB + B 16KB
static constexpr int SMEM_BYTES  = STAGES * STAGE_WORDS * 4;   // 98304

static constexpr int TILES_M = MDIM / 128;    // 64
static constexpr int TILES_N = NDIM / 128;    // 96
static constexpr int GROUP_M = 32;

// pack: one thread = one (kc16-PAIR, t16, lane) -> 2 units
static constexpr int A_PACK_BLOCKS = 8192;    // 2097152 threads
static constexpr int B_PACK_BLOCKS = 12288;   // 3145728 threads

__device__ __forceinline__ uint32_t smem_u32(const void* p) {
    return (uint32_t)__cvta_generic_to_shared(p);
}
__device__ __forceinline__ void cp16(uint32_t dst, const void* src) {
    asm volatile("cp.async.cg.shared.global [%0], [%1], 16;" :: "r"(dst), "l"(src));
}
__device__ __forceinline__ uint32_t h2pack(float lo, float hi) {
    __half2 h = __floats2half2_rn(lo, hi);
    return *reinterpret_cast<uint32_t*>(&h);
}
__device__ __forceinline__ void mma_f16(float* c, const uint32_t* a,
                                        uint32_t b0, uint32_t b1) {
    asm volatile(
        "mma.sync.aligned.m16n8k16.row.col.f32.f16.f16.f32 "
        "{%0,%1,%2,%3}, {%4,%5,%6,%7}, {%8,%9}, {%0,%1,%2,%3};"
        : "+f"(c[0]), "+f"(c[1]), "+f"(c[2]), "+f"(c[3])
        : "r"(a[0]), "r"(a[1]), "r"(a[2]), "r"(a[3]), "r"(b0), "r"(b1));
}

// ---------------- fused pack kernel: kc16-pairs (full 128B sector reads) ----
// Per thread: rows (t*16+gid, +8), k in [kc32*32, +32): 8 float2 loads that,
// across tig 0..3, cover two full 128B sectors per row; writes 2 units.
__global__ __launch_bounds__(256)
void pack_ab(const float* __restrict__ xsrc, const float* __restrict__ wsrc,
             uint32_t* __restrict__ dstA, uint32_t* __restrict__ dstB) {
    const bool isA = blockIdx.x < A_PACK_BLOCKS;
    const uint32_t idx = (isA ? blockIdx.x : blockIdx.x - A_PACK_BLOCKS) * 256u
                         + threadIdx.x;
    const int lane = idx & 31;
    const uint32_t unitp = idx >> 5;           // kc16-pair unit index
    const int T16   = isA ? MT16 : NT16;
    const int t16   = (int)(unitp % (uint32_t)T16);
    const int kc32  = (int)(unitp / (uint32_t)T16);   // 0..127
    const int gid = lane >> 2, tig = lane & 3;

    const float* src = isA ? xsrc : wsrc;
    const float* r0 = src + (size_t)(t16 * 16 + gid) * KDIM + kc32 * 32 + 2 * tig;
    const float* r1 = r0 + 8 * (size_t)KDIM;

    // kc16 = 2*kc32 (k offsets 0,8) and 2*kc32+1 (k offsets 16,24)
    float2 p00 = *reinterpret_cast<const float2*>(r0);        // row,   k
    float2 p01 = *reinterpret_cast<const float2*>(r0 + 8);    // row,   k+8
    float2 p02 = *reinterpret_cast<const float2*>(r0 + 16);   // row,   k+16
    float2 p03 = *reinterpret_cast<const float2*>(r0 + 24);   // row,   k+24
    float2 p10 = *reinterpret_cast<const float2*>(r1);        // row+8, k
    float2 p11 = *reinterpret_cast<const float2*>(r1 + 8);
    float2 p12 = *reinterpret_cast<const float2*>(r1 + 16);
    float2 p13 = *reinterpret_cast<const float2*>(r1 + 24);

    uint4 w0, w1;
    if (isA) {
        // A words: {a0,a1,a2,a3} = {(r,k),(r+8,k),(r,k+8),(r+8,k+8)}
        w0.x = h2pack(p00.x, p00.y);  w0.y = h2pack(p10.x, p10.y);
        w0.z = h2pack(p01.x, p01.y);  w0.w = h2pack(p11.x, p11.y);
        w1.x = h2pack(p02.x, p02.y);  w1.y = h2pack(p12.x, p12.y);
        w1.z = h2pack(p03.x, p03.y);  w1.w = h2pack(p13.x, p13.y);
        const size_t u0 = ((size_t)(2 * kc32) * MT16 + t16) * 32 + lane;
        const size_t u1 = u0 + (size_t)MT16 * 32;
        reinterpret_cast<uint4*>(dstA)[u0] = w0;
        reinterpret_cast<uint4*>(dstA)[u1] = w1;
    } else {
        // B words: {b0lo,b1lo,b0hi,b1hi} = {(n,k),(n,k+8),(n+8,k),(n+8,k+8)}
        w0.x = h2pack(p00.x, p00.y);  w0.y = h2pack(p01.x, p01.y);
        w0.z = h2pack(p10.x, p10.y);  w0.w = h2pack(p11.x, p11.y);
        w1.x = h2pack(p02.x, p02.y);  w1.y = h2pack(p03.x, p03.y);
        w1.z = h2pack(p12.x, p12.y);  w1.w = h2pack(p13.x, p13.y);
        const size_t u0 = ((size_t)(2 * kc32) * NT16 + t16) * 32 + lane;
        const size_t u1 = u0 + (size_t)NT16 * 32;
        reinterpret_cast<uint4*>(dstB)[u0] = w0;
        reinterpret_cast<uint4*>(dstB)[u1] = w1;
    }
}

// ---------------- GEMM: R11 core, byte-identical ----------------
// stage layout (words): A [kc16(4)][mtile(8)][lane(32)][q(4)] = 4096,
//                       B [kc16(4)][ntile(8)][lane(32)][q(4)] = 4096 at +4096.
__global__ __launch_bounds__(THREADS, 2)
void gemm_f16(const uint32_t* __restrict__ Apack,
              const uint32_t* __restrict__ Bpack,
              const float* __restrict__ bias,
              float* __restrict__ out)
{
    extern __shared__ uint32_t smemu[];
    const uint32_t sbase = smem_u32(smemu);

    const int tid  = threadIdx.x;
    const int wid  = tid >> 5;
    const int lane = tid & 31;
    const int gid  = lane >> 2;
    const int tig  = lane & 3;
    const int warp_m = wid & 1;     // 64 rows
    const int warp_n = wid >> 1;    // 64 cols

    const int bid  = blockIdx.x;
    const int band = bid / (GROUP_M * TILES_N);
    const int rem  = bid % (GROUP_M * TILES_N);
    const int mt   = band * GROUP_M + (rem % GROUP_M);
    const int nt   = rem / GROUP_M;
    const int m0 = mt * 128;
    const int n0 = nt * 128;

    const int mtBase = m0 >> 4;
    const int ntBase = n0 >> 4;

    float acc[4][8][4];
#pragma unroll
    for (int mi = 0; mi < 4; mi++)
#pragma unroll
        for (int ni = 0; ni < 8; ni++)
#pragma unroll
            for (int q = 0; q < 4; q++) acc[mi][ni][q] = 0.0f;

    const int KT = KDIM / 64;       // 64
    const int aBase = warp_m * 4;
    const int bBase = warp_n * 4;

    auto load_stage = [&](int slot, int kt) {
        const uint32_t sA = sbase + (uint32_t)(slot * STAGE_WORDS) * 4;
        const uint32_t sB = sA + 4096 * 4;
#pragma unroll
        for (int kc = 0; kc < 4; kc++) {
            const uint32_t* aS = Apack + ((size_t)(4 * kt + kc) * MT16 + mtBase) * 128;
            const uint32_t* bS = Bpack + ((size_t)(4 * kt + kc) * NT16 + ntBase) * 128;
            cp16(sA + kc * 4096 + tid * 32,      aS + tid * 8);
            cp16(sA + kc * 4096 + tid * 32 + 16, aS + tid * 8 + 4);
            cp16(sB + kc * 4096 + tid * 32,      bS + tid * 8);
            cp16(sB + kc * 4096 + tid * 32 + 16, bS + tid * 8 + 4);
        }
        asm volatile("cp.async.commit_group;" ::: "memory");
    };

#pragma unroll
    for (int s = 0; s < STAGES - 1; s++) load_stage(s, s);

    uint4 af[2][4], bf[2][4];

    asm volatile("cp.async.wait_group %0;" :: "n"(STAGES - 2) : "memory");
    __syncthreads();
    {
        const uint32_t* as = smemu;
        const uint32_t* bs = as + 4096;
#pragma unroll
        for (int mi = 0; mi < 4; mi++)
            af[0][mi] = *reinterpret_cast<const uint4*>(
                as + (aBase + mi) * 128 + lane * 4);
#pragma unroll
        for (int nj = 0; nj < 4; nj++)
            bf[0][nj] = *reinterpret_cast<const uint4*>(
                bs + (bBase + nj) * 128 + lane * 4);
    }

    for (int kt = 0; kt < KT; kt++) {
        const uint32_t* as = smemu + (kt % STAGES) * STAGE_WORDS;
        const uint32_t* bs = as + 4096;

        const int kin = kt + STAGES - 1;
        if (kin < KT) load_stage(kin % STAGES, kin);
        else asm volatile("cp.async.commit_group;" ::: "memory");

        // ---- ks = 0..2: prefetch next frags, compute current ----
#pragma unroll
        for (int ks = 0; ks < 3; ks++) {
            const int cur = ks & 1;
            const int nxt = cur ^ 1;
#pragma unroll
            for (int mi = 0; mi < 4; mi++)
                af[nxt][mi] = *reinterpret_cast<const uint4*>(
                    as + ((ks + 1) * 8 + aBase + mi) * 128 + lane * 4);
#pragma unroll
            for (int nj = 0; nj < 4; nj++)
                bf[nxt][nj] = *reinterpret_cast<const uint4*>(
                    bs + ((ks + 1) * 8 + bBase + nj) * 128 + lane * 4);
#pragma unroll
            for (int mi = 0; mi < 4; mi++) {
                const uint32_t afr[4] = {af[cur][mi].x, af[cur][mi].y,
                                         af[cur][mi].z, af[cur][mi].w};
#pragma unroll
                for (int nj = 0; nj < 4; nj++) {
                    mma_f16(acc[mi][nj * 2 + 0], afr, bf[cur][nj].x, bf[cur][nj].y);
                    mma_f16(acc[mi][nj * 2 + 1], afr, bf[cur][nj].z, bf[cur][nj].w);
                }
            }
        }

        // ---- stage-kt smem reads done; publish stage kt+1, license slot reuse ----
        asm volatile("cp.async.wait_group %0;" :: "n"(STAGES - 2) : "memory");
        __syncthreads();

        // ---- prefetch (kt+1, ks0) into buf0 ----
        if (kt + 1 < KT) {
            const uint32_t* as2 = smemu + ((kt + 1) % STAGES) * STAGE_WORDS;
            const uint32_t* bs2 = as2 + 4096;
#pragma unroll
            for (int mi = 0; mi < 4; mi++)
                af[0][mi] = *reinterpret_cast<const uint4*>(
                    as2 + (aBase + mi) * 128 + lane * 4);
#pragma unroll
            for (int nj = 0; nj < 4; nj++)
                bf[0][nj] = *reinterpret_cast<const uint4*>(
                    bs2 + (bBase + nj) * 128 + lane * 4);
        }

        // ---- ks = 3 MMAs (buf1), covering the prefetch latency ----
#pragma unroll
        for (int mi = 0; mi < 4; mi++) {
            const uint32_t afr[4] = {af[1][mi].x, af[1][mi].y,
                                     af[1][mi].z, af[1][mi].w};
#pragma unroll
            for (int nj = 0; nj < 4; nj++) {
                mma_f16(acc[mi][nj * 2 + 0], afr, bf[1][nj].x, bf[1][nj].y);
                mma_f16(acc[mi][nj * 2 + 1], afr, bf[1][nj].z, bf[1][nj].w);
            }
        }
    }

    // ---- epilogue: bias + segmented store ----
    const int seg  = n0 / HDIM;
    const int nloc = n0 % HDIM;
    float* outseg = out + (size_t)seg * MDIM * HDIM;

#pragma unroll
    for (int ni = 0; ni < 8; ni++) {
        const int cofs = warp_n * 64 + (ni >> 1) * 16 + (ni & 1) * 8 + 2 * tig;
        const float b0 = __ldg(bias + n0 + cofs);
        const float b1 = __ldg(bias + n0 + cofs + 1);
        const int cn = nloc + cofs;
#pragma unroll
        for (int mi = 0; mi < 4; mi++) {
            const int gm = m0 + warp_m * 64 + mi * 16 + gid;
            float2 v0, v1;
            v0.x = acc[mi][ni][0] + b0;  v0.y = acc[mi][ni][1] + b1;
            v1.x = acc[mi][ni][2] + b0;  v1.y = acc[mi][ni][3] + b1;
            *reinterpret_cast<float2*>(outseg + (size_t)gm * HDIM + cn)       = v0;
            *reinterpret_cast<float2*>(outseg + (size_t)(gm + 8) * HDIM + cn) = v1;
        }
    }
}

extern "C" void kernel_launch(void* const* d_in, const int* in_sizes, int n_in,
                              void* d_out, int out_size)
{
    const float* x = (const float*)d_in[0];
    const float* W = (const float*)d_in[1];
    const float* b = (const float*)d_in[2];
    float* out = (float*)d_out;

    void *ap, *bp;
    cudaGetSymbolAddress(&ap, g_Apack);
    cudaGetSymbolAddress(&bp, g_Bpack);

    pack_ab<<<A_PACK_BLOCKS + B_PACK_BLOCKS, 256>>>(
        x, W, (uint32_t*)ap, (uint32_t*)bp);

    cudaFuncSetAttribute(gemm_f16, cudaFuncAttributeMaxDynamicSharedMemorySize, SMEM_BYTES);
    gemm_f16<<<TILES_M * TILES_N, THREADS, SMEM_BYTES>>>(
        (const uint32_t*)ap, (const uint32_t*)bp, b, out);
}

// round 14
// speedup vs baseline: 1.1149x; 1.0285x over previous
#include <cuda_runtime.h>
#include <cuda_fp16.h>
#include <cstdint>
#include <cstddef>

// ---------------------------------------------------------------------------
// Fused concat-linear, single-pass FP16 mma.sync.m16n8k16 (fp32 accumulate),
// fragment-packed operands. R14 = R13 + mainloop strength reduction:
// incremental gmem pointers (no per-kt IMAD chains) and kt-loop unroll-by-3
// (STAGES=3 -> all %3 slot indices constant-folded).
//   y[m,o] = sum_k x[m,k] W[o,k] + b[o];  M=8192 N=12288 K=4096
//   out = 3 segments of H=4096 along o.
// ---------------------------------------------------------------------------

#define MDIM 8192
#define NDIM 12288
#define KDIM 4096
#define HDIM 4096

static constexpr int STAGES = 3;
static constexpr int THREADS = 128;

static constexpr int MT16 = MDIM / 16;        // 512
static constexpr int NT16 = NDIM / 16;        // 768
static constexpr int KC16 = KDIM / 16;        // 256

// packed half2-word scratch, fragment-ordered (validated R10+):
// A unit (kc16, mt16): 32 lanes x 4 words {a0,a1,a2,a3} of m16n8k16.row
// B unit (kc16, nt16): 32 lanes x 4 words {b0lo,b1lo,b0hi,b1hi}
__device__ uint32_t g_Apack[(size_t)KC16 * MT16 * 128];   // 67 MB
__device__ uint32_t g_Bpack[(size_t)KC16 * NT16 * 128];   // 100 MB

static constexpr int STAGE_WORDS = 8192;                       // A 16KB + B 16KB
static constexpr int SMEM_BYTES  = STAGES * STAGE_WORDS * 4;   // 98304

static constexpr int TILES_M = MDIM / 128;    // 64
static constexpr int TILES_N = NDIM / 128;    // 96
static constexpr int GROUP_M = 32;

static constexpr int A_PACK_BLOCKS = 8192;    // 2097152 threads
static constexpr int B_PACK_BLOCKS = 12288;   // 3145728 threads

// per-kt gmem strides (words)
static constexpr size_t A_KT_STEP = (size_t)4 * MT16 * 128;   // 262144
static constexpr size_t B_KT_STEP = (size_t)4 * NT16 * 128;   // 393216
static constexpr size_t A_KC_STEP = (size_t)MT16 * 128;       // 65536
static constexpr size_t B_KC_STEP = (size_t)NT16 * 128;       // 98304

__device__ __forceinline__ uint32_t smem_u32(const void* p) {
    return (uint32_t)__cvta_generic_to_shared(p);
}
__device__ __forceinline__ void cp16(uint32_t dst, const void* src) {
    asm volatile("cp.async.cg.shared.global [%0], [%1], 16;" :: "r"(dst), "l"(src));
}
__device__ __forceinline__ uint32_t h2pack(float lo, float hi) {
    __half2 h = __floats2half2_rn(lo, hi);
    return *reinterpret_cast<uint32_t*>(&h);
}
__device__ __forceinline__ void mma_f16(float* c, const uint32_t* a,
                                        uint32_t b0, uint32_t b1) {
    asm volatile(
        "mma.sync.aligned.m16n8k16.row.col.f32.f16.f16.f32 "
        "{%0,%1,%2,%3}, {%4,%5,%6,%7}, {%8,%9}, {%0,%1,%2,%3};"
        : "+f"(c[0]), "+f"(c[1]), "+f"(c[2]), "+f"(c[3])
        : "r"(a[0]), "r"(a[1]), "r"(a[2]), "r"(a[3]), "r"(b0), "r"(b1));
}

// ---------------- fused pack kernel (unchanged, validated R13) ----------------
__global__ __launch_bounds__(256)
void pack_ab(const float* __restrict__ xsrc, const float* __restrict__ wsrc,
             uint32_t* __restrict__ dstA, uint32_t* __restrict__ dstB) {
    const bool isA = blockIdx.x < A_PACK_BLOCKS;
    const uint32_t idx = (isA ? blockIdx.x : blockIdx.x - A_PACK_BLOCKS) * 256u
                         + threadIdx.x;
    const int lane = idx & 31;
    const uint32_t unitp = idx >> 5;
    const int T16   = isA ? MT16 : NT16;
    const int t16   = (int)(unitp % (uint32_t)T16);
    const int kc32  = (int)(unitp / (uint32_t)T16);
    const int gid = lane >> 2, tig = lane & 3;

    const float* src = isA ? xsrc : wsrc;
    const float* r0 = src + (size_t)(t16 * 16 + gid) * KDIM + kc32 * 32 + 2 * tig;
    const float* r1 = r0 + 8 * (size_t)KDIM;

    float2 p00 = *reinterpret_cast<const float2*>(r0);
    float2 p01 = *reinterpret_cast<const float2*>(r0 + 8);
    float2 p02 = *reinterpret_cast<const float2*>(r0 + 16);
    float2 p03 = *reinterpret_cast<const float2*>(r0 + 24);
    float2 p10 = *reinterpret_cast<const float2*>(r1);
    float2 p11 = *reinterpret_cast<const float2*>(r1 + 8);
    float2 p12 = *reinterpret_cast<const float2*>(r1 + 16);
    float2 p13 = *reinterpret_cast<const float2*>(r1 + 24);

    uint4 w0, w1;
    if (isA) {
        w0.x = h2pack(p00.x, p00.y);  w0.y = h2pack(p10.x, p10.y);
        w0.z = h2pack(p01.x, p01.y);  w0.w = h2pack(p11.x, p11.y);
        w1.x = h2pack(p02.x, p02.y);  w1.y = h2pack(p12.x, p12.y);
        w1.z = h2pack(p03.x, p03.y);  w1.w = h2pack(p13.x, p13.y);
        const size_t u0 = ((size_t)(2 * kc32) * MT16 + t16) * 32 + lane;
        const size_t u1 = u0 + (size_t)MT16 * 32;
        reinterpret_cast<uint4*>(dstA)[u0] = w0;
        reinterpret_cast<uint4*>(dstA)[u1] = w1;
    } else {
        w0.x = h2pack(p00.x, p00.y);  w0.y = h2pack(p01.x, p01.y);
        w0.z = h2pack(p10.x, p10.y);  w0.w = h2pack(p11.x, p11.y);
        w1.x = h2pack(p02.x, p02.y);  w1.y = h2pack(p03.x, p03.y);
        w1.z = h2pack(p12.x, p12.y);  w1.w = h2pack(p13.x, p13.y);
        const size_t u0 = ((size_t)(2 * kc32) * NT16 + t16) * 32 + lane;
        const size_t u1 = u0 + (size_t)NT16 * 32;
        reinterpret_cast<uint4*>(dstB)[u0] = w0;
        reinterpret_cast<uint4*>(dstB)[u1] = w1;
    }
}

// ---------------- GEMM: R13 pipeline + strength-reduced addressing ----------------
// stage layout (words): A [kc16(4)][mtile(8)][lane(32)][q(4)] = 4096,
//                       B [kc16(4)][ntile(8)][lane(32)][q(4)] = 4096 at +4096.
__global__ __launch_bounds__(THREADS, 2)
void gemm_f16(const uint32_t* __restrict__ Apack,
              const uint32_t* __restrict__ Bpack,
              const float* __restrict__ bias,
              float* __restrict__ out)
{
    extern __shared__ uint32_t smemu[];
    const uint32_t sbase = smem_u32(smemu);

    const int tid  = threadIdx.x;
    const int wid  = tid >> 5;
    const int lane = tid & 31;
    const int gid  = lane >> 2;
    const int tig  = lane & 3;
    const int warp_m = wid & 1;     // 64 rows
    const int warp_n = wid >> 1;    // 64 cols

    const int bid  = blockIdx.x;
    const int band = bid / (GROUP_M * TILES_N);
    const int rem  = bid % (GROUP_M * TILES_N);
    const int mt   = band * GROUP_M + (rem % GROUP_M);
    const int nt   = rem / GROUP_M;
    const int m0 = mt * 128;
    const int n0 = nt * 128;

    float acc[4][8][4];
#pragma unroll
    for (int mi = 0; mi < 4; mi++)
#pragma unroll
        for (int ni = 0; ni < 8; ni++)
#pragma unroll
            for (int q = 0; q < 4; q++) acc[mi][ni][q] = 0.0f;

    const int KT = KDIM / 64;       // 64
    const int aBase = warp_m * 4;
    const int bBase = warp_n * 4;

    // incremental gmem cursors (thread-local element pointers)
    const uint32_t* aNext = Apack + (size_t)(m0 >> 4) * 128 + tid * 8;
    const uint32_t* bNext = Bpack + (size_t)(n0 >> 4) * 128 + tid * 8;

    // stage loader from explicit cursors; advances them by one kt
    auto load_stage = [&](int slot) {
        const uint32_t sA = sbase + (uint32_t)(slot * STAGE_WORDS) * 4;
        const uint32_t sB = sA + 4096 * 4;
#pragma unroll
        for (int kc = 0; kc < 4; kc++) {
            cp16(sA + kc * 4096 + tid * 32,      aNext + kc * A_KC_STEP);
            cp16(sA + kc * 4096 + tid * 32 + 16, aNext + kc * A_KC_STEP + 4);
            cp16(sB + kc * 4096 + tid * 32,      bNext + kc * B_KC_STEP);
            cp16(sB + kc * 4096 + tid * 32 + 16, bNext + kc * B_KC_STEP + 4);
        }
        aNext += A_KT_STEP;
        bNext += B_KT_STEP;
        asm volatile("cp.async.commit_group;" ::: "memory");
    };

#pragma unroll
    for (int s = 0; s < STAGES - 1; s++) load_stage(s);

    uint4 af[2][4], bf[2][4];

    asm volatile("cp.async.wait_group %0;" :: "n"(STAGES - 2) : "memory");
    __syncthreads();
    {
        const uint32_t* as = smemu;
        const uint32_t* bs = as + 4096;
#pragma unroll
        for (int mi = 0; mi < 4; mi++)
            af[0][mi] = *reinterpret_cast<const uint4*>(
                as + (aBase + mi) * 128 + lane * 4);
#pragma unroll
        for (int nj = 0; nj < 4; nj++)
            bf[0][nj] = *reinterpret_cast<const uint4*>(
                bs + (bBase + nj) * 128 + lane * 4);
    }

#pragma unroll 3
    for (int kt = 0; kt < KT; kt++) {
        const uint32_t* as = smemu + (kt % STAGES) * STAGE_WORDS;
        const uint32_t* bs = as + 4096;

        const int kin = kt + STAGES - 1;
        if (kin < KT) load_stage(kin % STAGES);
        else asm volatile("cp.async.commit_group;" ::: "memory");

        // ---- ks = 0..2: prefetch next frags, compute current ----
#pragma unroll
        for (int ks = 0; ks < 3; ks++) {
            const int cur = ks & 1;
            const int nxt = cur ^ 1;
#pragma unroll
            for (int mi = 0; mi < 4; mi++)
                af[nxt][mi] = *reinterpret_cast<const uint4*>(
                    as + ((ks + 1) * 8 + aBase + mi) * 128 + lane * 4);
#pragma unroll
            for (int nj = 0; nj < 4; nj++)
                bf[nxt][nj] = *reinterpret_cast<const uint4*>(
                    bs + ((ks + 1) * 8 + bBase + nj) * 128 + lane * 4);
#pragma unroll
            for (int mi = 0; mi < 4; mi++) {
                const uint32_t afr[4] = {af[cur][mi].x, af[cur][mi].y,
                                         af[cur][mi].z, af[cur][mi].w};
#pragma unroll
                for (int nj = 0; nj < 4; nj++) {
                    mma_f16(acc[mi][nj * 2 + 0], afr, bf[cur][nj].x, bf[cur][nj].y);
                    mma_f16(acc[mi][nj * 2 + 1], afr, bf[cur][nj].z, bf[cur][nj].w);
                }
            }
        }

        // ---- stage-kt smem reads done; publish stage kt+1, license slot reuse ----
        asm volatile("cp.async.wait_group %0;" :: "n"(STAGES - 2) : "memory");
        __syncthreads();

        // ---- prefetch (kt+1, ks0) into buf0 ----
        if (kt + 1 < KT) {
            const uint32_t* as2 = smemu + ((kt + 1) % STAGES) * STAGE_WORDS;
            const uint32_t* bs2 = as2 + 4096;
#pragma unroll
            for (int mi = 0; mi < 4; mi++)
                af[0][mi] = *reinterpret_cast<const uint4*>(
                    as2 + (aBase + mi) * 128 + lane * 4);
#pragma unroll
            for (int nj = 0; nj < 4; nj++)
                bf[0][nj] = *reinterpret_cast<const uint4*>(
                    bs2 + (bBase + nj) * 128 + lane * 4);
        }

        // ---- ks = 3 MMAs (buf1), covering the prefetch latency ----
#pragma unroll
        for (int mi = 0; mi < 4; mi++) {
            const uint32_t afr[4] = {af[1][mi].x, af[1][mi].y,
                                     af[1][mi].z, af[1][mi].w};
#pragma unroll
            for (int nj = 0; nj < 4; nj++) {
                mma_f16(acc[mi][nj * 2 + 0], afr, bf[1][nj].x, bf[1][nj].y);
                mma_f16(acc[mi][nj * 2 + 1], afr, bf[1][nj].z, bf[1][nj].w);
            }
        }
    }

    // ---- epilogue: bias + segmented store (unchanged) ----
    const int seg  = n0 / HDIM;
    const int nloc = n0 % HDIM;
    float* outseg = out + (size_t)seg * MDIM * HDIM;

#pragma unroll
    for (int ni = 0; ni < 8; ni++) {
        const int cofs = warp_n * 64 + (ni >> 1) * 16 + (ni & 1) * 8 + 2 * tig;
        const float b0 = __ldg(bias + n0 + cofs);
        const float b1 = __ldg(bias + n0 + cofs + 1);
        const int cn = nloc + cofs;
#pragma unroll
        for (int mi = 0; mi < 4; mi++) {
            const int gm = m0 + warp_m * 64 + mi * 16 + gid;
            float2 v0, v1;
            v0.x = acc[mi][ni][0] + b0;  v0.y = acc[mi][ni][1] + b1;
            v1.x = acc[mi][ni][2] + b0;  v1.y = acc[mi][ni][3] + b1;
            *reinterpret_cast<float2*>(outseg + (size_t)gm * HDIM + cn)       = v0;
            *reinterpret_cast<float2*>(outseg + (size_t)(gm + 8) * HDIM + cn) = v1;
        }
    }
}

extern "C" void kernel_launch(void* const* d_in, const int* in_sizes, int n_in,
                              void* d_out, int out_size)
{
    const float* x = (const float*)d_in[0];
    const float* W = (const float*)d_in[1];
    const float* b = (const float*)d_in[2];
    float* out = (float*)d_out;

    void *ap, *bp;
    cudaGetSymbolAddress(&ap, g_Apack);
    cudaGetSymbolAddress(&bp, g_Bpack);

    pack_ab<<<A_PACK_BLOCKS + B_PACK_BLOCKS, 256>>>(
        x, W, (uint32_t*)ap, (uint32_t*)bp);

    cudaFuncSetAttribute(gemm_f16, cudaFuncAttributeMaxDynamicSharedMemorySize, SMEM_BYTES);
    gemm_f16<<<TILES_M * TILES_N, THREADS, SMEM_BYTES>>>(
        (const uint32_t*)ap, (const uint32_t*)bp, b, out);
}